// round 1
// baseline (speedup 1.0000x reference)
#include <cuda_runtime.h>
#include <math.h>

#define NN 50000
#define EE 800000
#define HD 128
#define GG 64

// ---------------- scratch (device globals: allocation-free) ----------------
__device__ float g_z[NN * HD];        // GEMM output (dinv-scaled)
__device__ float g_h[NN * HD];        // node features between layers
__device__ float g_dinv[NN];
__device__ int   g_degi[NN];          // incoming (non-self) edge counts
__device__ int   g_rowptr[NN + 1];
__device__ int   g_cursor[NN];
__device__ int   g_col[EE];           // src node per CSR slot (keyed by dst)
__device__ int   g_bsum[64];          // scan block sums
__device__ float g_f[GG * HD];        // pooled features
__device__ float g_t1[GG * 1024];
__device__ float g_t2[GG * 512];
__device__ float g_t3[GG * 256];
__device__ float g_t4[GG * HD];

// ---------------- CSR build ----------------
__global__ void k_zero_deg() {
    int i = blockIdx.x * blockDim.x + threadIdx.x;
    if (i < NN) g_degi[i] = 0;
}

__global__ void k_count(const int* __restrict__ ei) {
    int e = blockIdx.x * blockDim.x + threadIdx.x;
    if (e < EE) atomicAdd(&g_degi[ei[EE + e]], 1);
}

// block-local exclusive scan of g_degi -> g_rowptr, block sums -> g_bsum
__global__ void k_scan1() {
    __shared__ int s[1024];
    int t = threadIdx.x;
    int i = blockIdx.x * 1024 + t;
    int v = (i < NN) ? g_degi[i] : 0;
    s[t] = v;
    __syncthreads();
    for (int off = 1; off < 1024; off <<= 1) {
        int x = (t >= off) ? s[t - off] : 0;
        __syncthreads();
        s[t] += x;
        __syncthreads();
    }
    if (i < NN) g_rowptr[i] = s[t] - v;      // exclusive, chunk-local
    if (t == 1023) g_bsum[blockIdx.x] = s[1023];
}

__global__ void k_scan2(int nb) {
    __shared__ int s[64];
    int t = threadIdx.x;
    int v = (t < nb) ? g_bsum[t] : 0;
    s[t] = v;
    __syncthreads();
    for (int off = 1; off < 64; off <<= 1) {
        int x = (t >= off) ? s[t - off] : 0;
        __syncthreads();
        s[t] += x;
        __syncthreads();
    }
    if (t < nb) g_bsum[t] = s[t] - v;        // exclusive over block sums
}

__global__ void k_scan3() {
    int i = blockIdx.x * 1024 + threadIdx.x;
    if (i < NN) {
        int rp = g_rowptr[i] + g_bsum[blockIdx.x];
        g_rowptr[i] = rp;
        g_cursor[i] = rp;
        g_dinv[i]   = rsqrtf((float)(g_degi[i] + 1));   // +1 self loop
    }
    if (i == 0) g_rowptr[NN] = EE;
}

__global__ void k_fill(const int* __restrict__ ei) {
    int e = blockIdx.x * blockDim.x + threadIdx.x;
    if (e < EE) {
        int src = ei[e];
        int dst = ei[EE + e];
        int p = atomicAdd(&g_cursor[dst], 1);
        g_col[p] = src;
    }
}

// ---------------- SGEMM: C[v][c] = dinv[v] * sum_k A[v][k]*B[k][c] ----------
// M x 128 @ 128 x 128.  BM=64 BN=128 BK=16 TM=8 TN=4, 256 threads.
__global__ __launch_bounds__(256) void k_gemm(const float* __restrict__ A,
                                              const float* __restrict__ B,
                                              float* __restrict__ C,
                                              int M) {
    __shared__ float  As[16][65];
    __shared__ float4 Bs[16][32];
    int tid  = threadIdx.x;
    int base = blockIdx.x * 64;
    int tm = tid >> 5;         // 0..7  (warp id)
    int tn = tid & 31;         // lane
    float acc[8][4];
#pragma unroll
    for (int i = 0; i < 8; i++)
#pragma unroll
        for (int j = 0; j < 4; j++) acc[i][j] = 0.f;

    int arow  = tid >> 2;          // 0..63
    int acol4 = (tid & 3) * 4;     // 0,4,8,12
    int brow  = tid >> 5;          // 0..7
    int bcol  = tid & 31;

    for (int k0 = 0; k0 < 128; k0 += 16) {
        float4 av;
        int gr = base + arow;
        if (gr < M) av = *(const float4*)(A + (size_t)gr * 128 + k0 + acol4);
        else        av = make_float4(0.f, 0.f, 0.f, 0.f);
        As[acol4 + 0][arow] = av.x;
        As[acol4 + 1][arow] = av.y;
        As[acol4 + 2][arow] = av.z;
        As[acol4 + 3][arow] = av.w;
        Bs[brow][bcol]     = *(const float4*)(B + (k0 + brow) * 128 + bcol * 4);
        Bs[brow + 8][bcol] = *(const float4*)(B + (k0 + brow + 8) * 128 + bcol * 4);
        __syncthreads();
#pragma unroll
        for (int kk = 0; kk < 16; kk++) {
            float4 b4 = Bs[kk][tn];
#pragma unroll
            for (int i = 0; i < 8; i++) {
                float a = As[kk][tm * 8 + i];
                acc[i][0] = fmaf(a, b4.x, acc[i][0]);
                acc[i][1] = fmaf(a, b4.y, acc[i][1]);
                acc[i][2] = fmaf(a, b4.z, acc[i][2]);
                acc[i][3] = fmaf(a, b4.w, acc[i][3]);
            }
        }
        __syncthreads();
    }
#pragma unroll
    for (int i = 0; i < 8; i++) {
        int r = base + tm * 8 + i;
        if (r < M) {
            float dv = g_dinv[r];
            float4 o;
            o.x = acc[i][0] * dv;
            o.y = acc[i][1] * dv;
            o.z = acc[i][2] * dv;
            o.w = acc[i][3] * dv;
            *(float4*)(C + (size_t)r * 128 + tn * 4) = o;
        }
    }
}

// ---------------- aggregation: one warp per node ----------------
// out[v] = dinv[v] * (z[v] + sum_{u in in(v)} z[u]) + bias ; optional relu
__global__ __launch_bounds__(256) void k_agg(const float* __restrict__ z,
                                             const float* __restrict__ bias,
                                             float* __restrict__ out,
                                             int relu) {
    int wid  = (blockIdx.x * blockDim.x + threadIdx.x) >> 5;
    int lane = threadIdx.x & 31;
    if (wid >= NN) return;
    const float4* z4 = (const float4*)z;
    float4 acc = z4[(size_t)wid * 32 + lane];   // self loop
    int beg = g_rowptr[wid];
    int end = g_rowptr[wid + 1];
    int j = beg;
    for (; j + 3 < end; j += 4) {
        int u0 = g_col[j], u1 = g_col[j + 1], u2 = g_col[j + 2], u3 = g_col[j + 3];
        float4 a = z4[(size_t)u0 * 32 + lane];
        float4 b = z4[(size_t)u1 * 32 + lane];
        float4 c = z4[(size_t)u2 * 32 + lane];
        float4 d = z4[(size_t)u3 * 32 + lane];
        acc.x += (a.x + b.x) + (c.x + d.x);
        acc.y += (a.y + b.y) + (c.y + d.y);
        acc.z += (a.z + b.z) + (c.z + d.z);
        acc.w += (a.w + b.w) + (c.w + d.w);
    }
    for (; j < end; j++) {
        float4 a = z4[(size_t)g_col[j] * 32 + lane];
        acc.x += a.x; acc.y += a.y; acc.z += a.z; acc.w += a.w;
    }
    float dv = g_dinv[wid];
    float4 bb = ((const float4*)bias)[lane];
    float4 r;
    r.x = fmaf(acc.x, dv, bb.x);
    r.y = fmaf(acc.y, dv, bb.y);
    r.z = fmaf(acc.z, dv, bb.z);
    r.w = fmaf(acc.w, dv, bb.w);
    if (relu) {
        r.x = fmaxf(r.x, 0.f); r.y = fmaxf(r.y, 0.f);
        r.z = fmaxf(r.z, 0.f); r.w = fmaxf(r.w, 0.f);
    }
    ((float4*)out)[(size_t)wid * 32 + lane] = r;
}

// ---------------- mean pool per graph ----------------
__global__ __launch_bounds__(128) void k_pool(const float* __restrict__ h,
                                              const int* __restrict__ batch,
                                              float* __restrict__ dout) {
    int g = blockIdx.x;
    int c = threadIdx.x;   // 0..127
    // lower_bound(batch, g) and lower_bound(batch, g+1)
    int lo = 0, hi = NN;
    while (lo < hi) { int m = (lo + hi) >> 1; if (batch[m] < g) lo = m + 1; else hi = m; }
    int start = lo;
    lo = 0; hi = NN;
    while (lo < hi) { int m = (lo + hi) >> 1; if (batch[m] < g + 1) lo = m + 1; else hi = m; }
    int end = lo;
    float s = 0.f;
    for (int v = start; v < end; v++) s += h[(size_t)v * 128 + c];
    float cnt = (float)(end - start);
    float val = s / fmaxf(cnt, 1.0f);
    g_f[g * 128 + c] = val;
    dout[g * 128 + c] = val;
}

// ---------------- MLP layer ----------------
__global__ __launch_bounds__(256) void k_fc(const float* __restrict__ in,
                                            const float* __restrict__ W,
                                            const float* __restrict__ b,
                                            float* __restrict__ out,
                                            int K, int C, int relu) {
    __shared__ float s_in[1024];
    int g = blockIdx.x;
    for (int k = threadIdx.x; k < K; k += blockDim.x) s_in[k] = in[g * K + k];
    __syncthreads();
    int c = blockIdx.y * blockDim.x + threadIdx.x;
    if (c < C) {
        float acc = b[c];
        for (int k = 0; k < K; k++) acc = fmaf(s_in[k], W[(size_t)k * C + c], acc);
        if (relu) acc = fmaxf(acc, 0.f);
        out[g * C + c] = acc;
    }
}

extern "C" void kernel_launch(void* const* d_in, const int* in_sizes, int n_in,
                              void* d_out, int out_size) {
    const float* x       = (const float*)d_in[0];
    const int*   ei      = (const int*)d_in[1];
    const int*   batch   = (const int*)d_in[2];
    const float* c1w = (const float*)d_in[3];
    const float* c1b = (const float*)d_in[4];
    const float* c2w = (const float*)d_in[5];
    const float* c2b = (const float*)d_in[6];
    const float* c3w = (const float*)d_in[7];
    const float* c3b = (const float*)d_in[8];
    const float* f1w = (const float*)d_in[9];
    const float* f1b = (const float*)d_in[10];
    const float* f2w = (const float*)d_in[11];
    const float* f2b = (const float*)d_in[12];
    const float* f3w = (const float*)d_in[13];
    const float* f3b = (const float*)d_in[14];
    const float* f4w = (const float*)d_in[15];
    const float* f4b = (const float*)d_in[16];
    const float* f5w = (const float*)d_in[17];
    const float* f5b = (const float*)d_in[18];
    float* dout = (float*)d_out;

    float *p_z, *p_h, *p_f, *p_t1, *p_t2, *p_t3, *p_t4;
    cudaGetSymbolAddress((void**)&p_z,  g_z);
    cudaGetSymbolAddress((void**)&p_h,  g_h);
    cudaGetSymbolAddress((void**)&p_f,  g_f);
    cudaGetSymbolAddress((void**)&p_t1, g_t1);
    cudaGetSymbolAddress((void**)&p_t2, g_t2);
    cudaGetSymbolAddress((void**)&p_t3, g_t3);
    cudaGetSymbolAddress((void**)&p_t4, g_t4);

    int nb = (NN + 1023) / 1024;

    // CSR + normalization build
    k_zero_deg<<<(NN + 255) / 256, 256>>>();
    k_count<<<(EE + 255) / 256, 256>>>(ei);
    k_scan1<<<nb, 1024>>>();
    k_scan2<<<1, 64>>>(nb);
    k_scan3<<<nb, 1024>>>();
    k_fill<<<(EE + 255) / 256, 256>>>(ei);

    int gemm_blocks = (NN + 63) / 64;
    int agg_blocks  = (NN * 32 + 255) / 256;

    // conv1
    k_gemm<<<gemm_blocks, 256>>>(x, c1w, p_z, NN);
    k_agg<<<agg_blocks, 256>>>(p_z, c1b, p_h, 1);
    // conv2
    k_gemm<<<gemm_blocks, 256>>>(p_h, c2w, p_z, NN);
    k_agg<<<agg_blocks, 256>>>(p_z, c2b, p_h, 1);
    // conv3 (no relu)
    k_gemm<<<gemm_blocks, 256>>>(p_h, c3w, p_z, NN);
    k_agg<<<agg_blocks, 256>>>(p_z, c3b, p_h, 0);

    // mean pool -> f (also first part of output)
    k_pool<<<GG, 128>>>(p_h, batch, dout);

    // MLP head
    k_fc<<<dim3(GG, (1024 + 255) / 256), 256>>>(p_f,  f1w, f1b, p_t1, 128,  1024, 1);
    k_fc<<<dim3(GG, (512  + 255) / 256), 256>>>(p_t1, f2w, f2b, p_t2, 1024, 512,  1);
    k_fc<<<dim3(GG, (256  + 255) / 256), 256>>>(p_t2, f3w, f3b, p_t3, 512,  256,  1);
    k_fc<<<dim3(GG, (128  + 255) / 256), 256>>>(p_t3, f4w, f4b, p_t4, 256,  128,  1);
    k_fc<<<dim3(GG, 1), 256>>>(p_t4, f5w, f5b, dout + GG * HD, 128, 10, 0);
}